// round 3
// baseline (speedup 1.0000x reference)
#include <cuda_runtime.h>

#define N_ALPHA 0.05f
#define N_BETA  0.95f
#define BC_TOT  128
#define NN      1024
#define HID     20

// scratch: h0..h3 and 1/rowsum
__device__ float g_h[4][BC_TOT * NN * HID];
__device__ float g_invrs[BC_TOT * NN];

static __device__ __forceinline__ unsigned long long fma2(unsigned long long a,
                                                          unsigned long long b,
                                                          unsigned long long c) {
    unsigned long long d;
    asm("fma.rn.f32x2 %0, %1, %2, %3;" : "=l"(d) : "l"(a), "l"(b), "l"(c));
    return d;
}
static __device__ __forceinline__ unsigned long long pack2(float x, float y) {
    unsigned long long d;
    asm("mov.b64 %0, {%1, %2};" : "=l"(d) : "f"(x), "f"(y));
    return d;
}
static __device__ __forceinline__ float2 unpack2(unsigned long long v) {
    float2 f;
    asm("mov.b64 {%0, %1}, %2;" : "=f"(f.x), "=f"(f.y) : "l"(v));
    return f;
}

// ---------------------------------------------------------------------------
// h0[bc][n][j] = sum_i x[b][i][n][c] * Ws[i][j] + bs[j]
// ---------------------------------------------------------------------------
__global__ void h0_kernel(const float* __restrict__ x,
                          const float* __restrict__ Ws,
                          const float* __restrict__ bs) {
    __shared__ float wsm[32 * HID];
    __shared__ float bsm[HID];
    int tid = threadIdx.x;
    for (int i = tid; i < 32 * HID; i += 256) wsm[i] = Ws[i];
    if (tid < HID) bsm[tid] = bs[tid];
    __syncthreads();

    int r = blockIdx.x * 256 + tid;          // 0..131071
    int c = r & 15;
    int n = (r >> 4) & 1023;
    int b = r >> 14;

    unsigned long long acc[10];
    const unsigned long long* bp = (const unsigned long long*)bsm;
#pragma unroll
    for (int j = 0; j < 10; j++) acc[j] = bp[j];

    const float* xp = x + (size_t)b * 32 * 16384 + n * 16 + c;
#pragma unroll
    for (int i = 0; i < 32; i++) {
        float xv = xp[(size_t)i * 16384];
        unsigned long long xv2 = pack2(xv, xv);
        const unsigned long long* wr = (const unsigned long long*)&wsm[i * HID];
#pragma unroll
        for (int j = 0; j < 10; j++) acc[j] = fma2(xv2, wr[j], acc[j]);
    }
    int bc = b * 16 + c;
    float* o = &g_h[0][((size_t)bc * NN + n) * HID];
#pragma unroll
    for (int j = 0; j < 10; j++) {
        float2 f = unpack2(acc[j]);
        o[2 * j] = f.x; o[2 * j + 1] = f.y;
    }
}

// ---------------------------------------------------------------------------
// propagation: fully barrier-free mainloop.
//   - entire h_src (1024 x 20 = 80KB) staged in smem once
//   - each thread owns ONE adjacency row, streams it from gmem into regs
//     with register double-buffering (no smem for adj, values used once)
// ---------------------------------------------------------------------------
template <bool FIRST>
static __device__ __forceinline__ void step1(float a, const float* hrow,
                                             unsigned long long* acc, float& rs) {
    if (FIRST) rs += a;
    unsigned long long a2 = pack2(a, a);
    const ulonglong2* hw2 = (const ulonglong2*)hrow;
    ulonglong2 q0 = hw2[0], q1 = hw2[1], q2 = hw2[2], q3 = hw2[3], q4 = hw2[4];
    acc[0] = fma2(a2, q0.x, acc[0]); acc[1] = fma2(a2, q0.y, acc[1]);
    acc[2] = fma2(a2, q1.x, acc[2]); acc[3] = fma2(a2, q1.y, acc[3]);
    acc[4] = fma2(a2, q2.x, acc[4]); acc[5] = fma2(a2, q2.y, acc[5]);
    acc[6] = fma2(a2, q3.x, acc[6]); acc[7] = fma2(a2, q3.y, acc[7]);
    acc[8] = fma2(a2, q4.x, acc[8]); acc[9] = fma2(a2, q4.y, acc[9]);
}

template <bool FIRST>
static __device__ __forceinline__ void chunk16(const float4& c0, const float4& c1,
                                               const float4& c2, const float4& c3,
                                               const float* hb,
                                               unsigned long long* acc, float& rs) {
    step1<FIRST>(c0.x, hb + 0 * HID, acc, rs);
    step1<FIRST>(c0.y, hb + 1 * HID, acc, rs);
    step1<FIRST>(c0.z, hb + 2 * HID, acc, rs);
    step1<FIRST>(c0.w, hb + 3 * HID, acc, rs);
    step1<FIRST>(c1.x, hb + 4 * HID, acc, rs);
    step1<FIRST>(c1.y, hb + 5 * HID, acc, rs);
    step1<FIRST>(c1.z, hb + 6 * HID, acc, rs);
    step1<FIRST>(c1.w, hb + 7 * HID, acc, rs);
    step1<FIRST>(c2.x, hb + 8 * HID, acc, rs);
    step1<FIRST>(c2.y, hb + 9 * HID, acc, rs);
    step1<FIRST>(c2.z, hb + 10 * HID, acc, rs);
    step1<FIRST>(c2.w, hb + 11 * HID, acc, rs);
    step1<FIRST>(c3.x, hb + 12 * HID, acc, rs);
    step1<FIRST>(c3.y, hb + 13 * HID, acc, rs);
    step1<FIRST>(c3.z, hb + 14 * HID, acc, rs);
    step1<FIRST>(c3.w, hb + 15 * HID, acc, rs);
}

template <bool FIRST>
__global__ void __launch_bounds__(256, 2)
prop_kernel(const float* __restrict__ adj, int src, int dst) {
    extern __shared__ float hs[];          // full h_src for this bc: 1024*20 floats
    int bc = blockIdx.y;
    int tid = threadIdx.x;

    const float* hp = &g_h[src][(size_t)bc * (NN * HID)];
#pragma unroll
    for (int k = 0; k < 20; k++)
        ((float4*)hs)[tid + k * 256] = ((const float4*)hp)[tid + k * 256];
    __syncthreads();                       // the ONLY barrier

    int v = blockIdx.x * 256 + tid;        // this thread's row
    const float* arow = adj + ((size_t)bc << 20) + ((size_t)v << 10);

    unsigned long long acc[10] = {0, 0, 0, 0, 0, 0, 0, 0, 0, 0};
    float rs = 0.f;

    float4 c0 = __ldcs((const float4*)arow + 0);
    float4 c1 = __ldcs((const float4*)arow + 1);
    float4 c2 = __ldcs((const float4*)arow + 2);
    float4 c3 = __ldcs((const float4*)arow + 3);

#pragma unroll 1
    for (int w0 = 0; w0 < NN - 16; w0 += 16) {
        const float4* np = (const float4*)(arow + w0 + 16);
        float4 n0 = __ldcs(np + 0);
        float4 n1 = __ldcs(np + 1);
        float4 n2 = __ldcs(np + 2);
        float4 n3 = __ldcs(np + 3);
        chunk16<FIRST>(c0, c1, c2, c3, hs + w0 * HID, acc, rs);
        c0 = n0; c1 = n1; c2 = n2; c3 = n3;
    }
    chunk16<FIRST>(c0, c1, c2, c3, hs + (NN - 16) * HID, acc, rs);

    float ir;
    if (FIRST) {
        ir = 1.f / (rs + 1.f);
        g_invrs[bc * NN + v] = ir;
    } else {
        ir = g_invrs[bc * NN + v];
    }

    const float* h0r = &g_h[0][((size_t)bc * NN + v) * HID];
    const float* sr = hs + v * HID;        // self term from smem
    float* outr = &g_h[dst][((size_t)bc * NN + v) * HID];

    float res[20];
#pragma unroll
    for (int j = 0; j < 10; j++) {
        float2 a = unpack2(acc[j]);
        res[2 * j]     = N_ALPHA * h0r[2 * j]     + N_BETA * (a.x + sr[2 * j]) * ir;
        res[2 * j + 1] = N_ALPHA * h0r[2 * j + 1] + N_BETA * (a.y + sr[2 * j + 1]) * ir;
    }
#pragma unroll
    for (int q = 0; q < 5; q++)
        ((float4*)outr)[q] = make_float4(res[4 * q], res[4 * q + 1],
                                         res[4 * q + 2], res[4 * q + 3]);
}

// ---------------------------------------------------------------------------
// out[bc][n][o] = sum_{p,j} h_p[bc][n][j] * We[(p*20+j)][o] + be[o]
// h rows staged through smem for coalesced gmem reads.
// ---------------------------------------------------------------------------
__global__ void __launch_bounds__(256) end_kernel(const float* __restrict__ We,
                                                  const float* __restrict__ be,
                                                  float* __restrict__ out) {
    __shared__ float wsm[80 * 32];
    __shared__ float bsm[32];
    __shared__ float hsm[256 * HID];
    int tid = threadIdx.x;
    for (int i = tid; i < 80 * 32; i += 256) wsm[i] = We[i];
    if (tid < 32) bsm[tid] = be[tid];

    int r0 = blockIdx.x * 256;             // rows r0..r0+255 of flat [131072][20]

    unsigned long long acc[16];
    const unsigned long long* bp = (const unsigned long long*)bsm;
    // (bsm written by threads <32; sync below covers it before use)
#pragma unroll
    for (int p = 0; p < 4; p++) {
        __syncthreads();
        const float4* src4 = (const float4*)(&g_h[p][0] + (size_t)r0 * HID);
#pragma unroll
        for (int k = 0; k < 5; k++)
            ((float4*)hsm)[tid + k * 256] = src4[tid + k * 256];
        __syncthreads();
        if (p == 0) {
#pragma unroll
            for (int o = 0; o < 16; o++) acc[o] = bp[o];
        }
        const float* hr = hsm + tid * HID;
#pragma unroll
        for (int j = 0; j < HID; j++) {
            float v = hr[j];
            unsigned long long v2 = pack2(v, v);
            const unsigned long long* wr =
                (const unsigned long long*)&wsm[(p * HID + j) * 32];
#pragma unroll
            for (int o = 0; o < 16; o++) acc[o] = fma2(v2, wr[o], acc[o]);
        }
    }

    float* op = out + ((size_t)r0 + tid) * 32;
#pragma unroll
    for (int o = 0; o < 16; o++) {
        float2 f = unpack2(acc[o]);
        op[2 * o] = f.x; op[2 * o + 1] = f.y;
    }
}

// ---------------------------------------------------------------------------
extern "C" void kernel_launch(void* const* d_in, const int* in_sizes, int n_in,
                              void* d_out, int out_size) {
    const float* x   = (const float*)d_in[0];
    const float* adj = (const float*)d_in[1];
    const float* Ws  = (const float*)d_in[2];
    const float* bs  = (const float*)d_in[3];
    const float* We  = (const float*)d_in[4];
    const float* be  = (const float*)d_in[5];
    float* out = (float*)d_out;

    const int HS_BYTES = NN * HID * sizeof(float);   // 81920
    cudaFuncSetAttribute(prop_kernel<true>,
                         cudaFuncAttributeMaxDynamicSharedMemorySize, HS_BYTES);
    cudaFuncSetAttribute(prop_kernel<false>,
                         cudaFuncAttributeMaxDynamicSharedMemorySize, HS_BYTES);

    h0_kernel<<<512, 256>>>(x, Ws, bs);
    prop_kernel<true ><<<dim3(4, 128), 256, HS_BYTES>>>(adj, 0, 1);
    prop_kernel<false><<<dim3(4, 128), 256, HS_BYTES>>>(adj, 1, 2);
    prop_kernel<false><<<dim3(4, 128), 256, HS_BYTES>>>(adj, 2, 3);
    end_kernel<<<512, 256>>>(We, be, out);
}

// round 4
// speedup vs baseline: 1.6649x; 1.6649x over previous
#include <cuda_runtime.h>

#define N_ALPHA 0.05f
#define N_BETA  0.95f
#define BC_TOT  128
#define NN      1024
#define HID     20
#define KC      16          // w per chunk
#define RPC     256         // rows per CTA
#define TPB     128         // threads per block (prop)

// scratch: h0..h3 and 1/rowsum
__device__ float g_h[4][BC_TOT * NN * HID];
__device__ float g_invrs[BC_TOT * NN];

static __device__ __forceinline__ unsigned long long fma2(unsigned long long a,
                                                          unsigned long long b,
                                                          unsigned long long c) {
    unsigned long long d;
    asm("fma.rn.f32x2 %0, %1, %2, %3;" : "=l"(d) : "l"(a), "l"(b), "l"(c));
    return d;
}
static __device__ __forceinline__ unsigned long long pack2(float x, float y) {
    unsigned long long d;
    asm("mov.b64 %0, {%1, %2};" : "=l"(d) : "f"(x), "f"(y));
    return d;
}
static __device__ __forceinline__ float2 unpack2(unsigned long long v) {
    float2 f;
    asm("mov.b64 {%0, %1}, %2;" : "=f"(f.x), "=f"(f.y) : "l"(v));
    return f;
}
static __device__ __forceinline__ unsigned smem_u32(const void* p) {
    unsigned a;
    asm("{ .reg .u64 t; cvta.to.shared.u64 t, %1; cvt.u32.u64 %0, t; }"
        : "=r"(a) : "l"(p));
    return a;
}
static __device__ __forceinline__ void cp16(unsigned dst, const void* src) {
    asm volatile("cp.async.cg.shared.global [%0], [%1], 16;" :: "r"(dst), "l"(src));
}
static __device__ __forceinline__ void cp_commit() {
    asm volatile("cp.async.commit_group;");
}
static __device__ __forceinline__ void cp_wait1() {
    asm volatile("cp.async.wait_group 1;");
}

// ---------------------------------------------------------------------------
// h0[bc][n][j] = sum_i x[b][i][n][c] * Ws[i][j] + bs[j]
// ---------------------------------------------------------------------------
__global__ void h0_kernel(const float* __restrict__ x,
                          const float* __restrict__ Ws,
                          const float* __restrict__ bs) {
    __shared__ float wsm[32 * HID];
    __shared__ float bsm[HID];
    int tid = threadIdx.x;
    for (int i = tid; i < 32 * HID; i += 256) wsm[i] = Ws[i];
    if (tid < HID) bsm[tid] = bs[tid];
    __syncthreads();

    int r = blockIdx.x * 256 + tid;
    int c = r & 15;
    int n = (r >> 4) & 1023;
    int b = r >> 14;

    unsigned long long acc[10];
    const unsigned long long* bp = (const unsigned long long*)bsm;
#pragma unroll
    for (int j = 0; j < 10; j++) acc[j] = bp[j];

    const float* xp = x + (size_t)b * 32 * 16384 + n * 16 + c;
#pragma unroll
    for (int i = 0; i < 32; i++) {
        float xv = xp[(size_t)i * 16384];
        unsigned long long xv2 = pack2(xv, xv);
        const unsigned long long* wr = (const unsigned long long*)&wsm[i * HID];
#pragma unroll
        for (int j = 0; j < 10; j++) acc[j] = fma2(xv2, wr[j], acc[j]);
    }
    int bc = b * 16 + c;
    float* o = &g_h[0][((size_t)bc * NN + n) * HID];
#pragma unroll
    for (int j = 0; j < 10; j++) {
        float2 f = unpack2(acc[j]);
        o[2 * j] = f.x; o[2 * j + 1] = f.y;
    }
}

// ---------------------------------------------------------------------------
// propagation, cp.async double-buffered.
//  block 128 threads, 256 rows/CTA (2 rows/thread), grid (4, 128).
//  smem: adj_s[2][256][20] fp32 (rows padded 16->20, conflict-free LDS.128),
//        hs_s[2][16*20]    (h chunk, warp-broadcast reads)
// ---------------------------------------------------------------------------
template <bool FIRST>
__global__ void __launch_bounds__(TPB, 4)
prop_kernel(const float* __restrict__ adj, int src, int dst) {
    __shared__ float adj_s[2][RPC][20];
    __shared__ float hs_s[2][KC * HID];

    int bc = blockIdx.y;
    int rowbase = blockIdx.x * RPC;
    int tid = threadIdx.x;

    const float* adjbc = adj + ((size_t)bc << 20) + ((size_t)rowbase << 10);
    const float* hp = &g_h[src][(size_t)bc * (NN * HID)];

    // precompute per-thread cp.async dst/src for the 8 adj granules + 1 h granule
    int grow[8], gq[8];
#pragma unroll
    for (int p = 0; p < 8; p++) {
        int g = tid + p * TPB;       // 0..1023 float4 granules
        grow[p] = g >> 2;
        gq[p] = (g & 3) << 2;
    }

    unsigned long long acc0[10] = {0,0,0,0,0,0,0,0,0,0};
    unsigned long long acc1[10] = {0,0,0,0,0,0,0,0,0,0};
    float rs0 = 0.f, rs1 = 0.f;

    // ---- issue chunk 0 into stage 0
    {
#pragma unroll
        for (int p = 0; p < 8; p++)
            cp16(smem_u32(&adj_s[0][grow[p]][gq[p]]),
                 adjbc + (size_t)grow[p] * NN + gq[p]);
        if (tid < 80)
            cp16(smem_u32(&hs_s[0][tid * 4]), hp + tid * 4);
        cp_commit();
    }

#pragma unroll 1
    for (int i = 0; i < NN / KC; i++) {
        int st = i & 1;
        // guard: stage st^1 fully consumed by compute(i-1) before overwrite
        __syncthreads();
        if (i + 1 < NN / KC) {
            int nst = st ^ 1;
            const float* asrc = adjbc + (i + 1) * KC;
#pragma unroll
            for (int p = 0; p < 8; p++)
                cp16(smem_u32(&adj_s[nst][grow[p]][gq[p]]),
                     asrc + (size_t)grow[p] * NN + gq[p]);
            if (tid < 80)
                cp16(smem_u32(&hs_s[nst][tid * 4]),
                     hp + (i + 1) * (KC * HID) + tid * 4);
            cp_commit();
            cp_wait1();
        } else {
            asm volatile("cp.async.wait_group 0;");
        }
        __syncthreads();

        // pull both adj row-chunks into registers (conflict-free LDS.128)
        float4 a0[4], a1[4];
        const float4* p0 = (const float4*)&adj_s[st][tid][0];
        const float4* p1 = (const float4*)&adj_s[st][tid + TPB][0];
#pragma unroll
        for (int q = 0; q < 4; q++) { a0[q] = p0[q]; a1[q] = p1[q]; }

        const float* hb = &hs_s[st][0];
#pragma unroll
        for (int w = 0; w < KC; w++) {
            float v0 = ((const float*)a0)[w];
            float v1 = ((const float*)a1)[w];
            if (FIRST) { rs0 += v0; rs1 += v1; }
            unsigned long long v02 = pack2(v0, v0);
            unsigned long long v12 = pack2(v1, v1);
            const ulonglong2* hw2 = (const ulonglong2*)(hb + w * HID);
            ulonglong2 q0 = hw2[0], q1 = hw2[1], q2 = hw2[2], q3 = hw2[3], q4 = hw2[4];
            unsigned long long hv[10] = {q0.x, q0.y, q1.x, q1.y, q2.x,
                                         q2.y, q3.x, q3.y, q4.x, q4.y};
#pragma unroll
            for (int j = 0; j < 10; j++) {
                acc0[j] = fma2(v02, hv[j], acc0[j]);
                acc1[j] = fma2(v12, hv[j], acc1[j]);
            }
        }
    }

    int v0 = rowbase + tid;
    int v1 = v0 + TPB;
    float ir0, ir1;
    if (FIRST) {
        ir0 = 1.f / (rs0 + 1.f);
        ir1 = 1.f / (rs1 + 1.f);
        g_invrs[bc * NN + v0] = ir0;
        g_invrs[bc * NN + v1] = ir1;
    } else {
        ir0 = g_invrs[bc * NN + v0];
        ir1 = g_invrs[bc * NN + v1];
    }

    const float* h0p = &g_h[0][(size_t)bc * (NN * HID)];
    float* ho = &g_h[dst][(size_t)bc * (NN * HID)];
#pragma unroll 2
    for (int rr = 0; rr < 2; rr++) {
        int v = rr ? v1 : v0;
        const unsigned long long* acc = rr ? acc1 : acc0;
        float ir = rr ? ir1 : ir0;
        const float* hpr = hp + v * HID;
        const float* h0r = h0p + v * HID;
        float* outr = ho + v * HID;
        float res[20];
#pragma unroll
        for (int j = 0; j < 10; j++) {
            float2 a = unpack2(acc[j]);
            res[2 * j]     = N_ALPHA * h0r[2 * j]     + N_BETA * (a.x + hpr[2 * j]) * ir;
            res[2 * j + 1] = N_ALPHA * h0r[2 * j + 1] + N_BETA * (a.y + hpr[2 * j + 1]) * ir;
        }
#pragma unroll
        for (int q = 0; q < 5; q++)
            ((float4*)outr)[q] = make_float4(res[4 * q], res[4 * q + 1],
                                             res[4 * q + 2], res[4 * q + 3]);
    }
}

// ---------------------------------------------------------------------------
// out[bc][n][o] = sum_{p,j} h_p[bc][n][j] * We[(p*20+j)][o] + be[o]
// ---------------------------------------------------------------------------
__global__ void __launch_bounds__(256) end_kernel(const float* __restrict__ We,
                                                  const float* __restrict__ be,
                                                  float* __restrict__ out) {
    __shared__ float wsm[80 * 32];
    __shared__ float bsm[32];
    __shared__ float hsm[256 * HID];
    int tid = threadIdx.x;
    for (int i = tid; i < 80 * 32; i += 256) wsm[i] = We[i];
    if (tid < 32) bsm[tid] = be[tid];

    int r0 = blockIdx.x * 256;

    unsigned long long acc[16];
    const unsigned long long* bp = (const unsigned long long*)bsm;
#pragma unroll
    for (int p = 0; p < 4; p++) {
        __syncthreads();
        const float4* src4 = (const float4*)(&g_h[p][0] + (size_t)r0 * HID);
#pragma unroll
        for (int k = 0; k < 5; k++)
            ((float4*)hsm)[tid + k * 256] = src4[tid + k * 256];
        __syncthreads();
        if (p == 0) {
#pragma unroll
            for (int o = 0; o < 16; o++) acc[o] = bp[o];
        }
        const float* hr = hsm + tid * HID;
#pragma unroll
        for (int j = 0; j < HID; j++) {
            float v = hr[j];
            unsigned long long v2 = pack2(v, v);
            const unsigned long long* wr =
                (const unsigned long long*)&wsm[(p * HID + j) * 32];
#pragma unroll
            for (int o = 0; o < 16; o++) acc[o] = fma2(v2, wr[o], acc[o]);
        }
    }

    float* op = out + ((size_t)r0 + tid) * 32;
#pragma unroll
    for (int o = 0; o < 16; o++) {
        float2 f = unpack2(acc[o]);
        op[2 * o] = f.x; op[2 * o + 1] = f.y;
    }
}

// ---------------------------------------------------------------------------
extern "C" void kernel_launch(void* const* d_in, const int* in_sizes, int n_in,
                              void* d_out, int out_size) {
    const float* x   = (const float*)d_in[0];
    const float* adj = (const float*)d_in[1];
    const float* Ws  = (const float*)d_in[2];
    const float* bs  = (const float*)d_in[3];
    const float* We  = (const float*)d_in[4];
    const float* be  = (const float*)d_in[5];
    float* out = (float*)d_out;

    h0_kernel<<<512, 256>>>(x, Ws, bs);
    prop_kernel<true ><<<dim3(4, 128), TPB>>>(adj, 0, 1);
    prop_kernel<false><<<dim3(4, 128), TPB>>>(adj, 1, 2);
    prop_kernel<false><<<dim3(4, 128), TPB>>>(adj, 2, 3);
    end_kernel<<<512, 256>>>(We, be, out);
}